// round 11
// baseline (speedup 1.0000x reference)
#include <cuda_runtime.h>
#include <math.h>

#define NB 8
#define SS 1024
#define EE 1024
#define DKK 512
#define DVV 512

#define NS_GROW 26      // a = 1.9 iterations
#define NS_POLISH 6     // a = 1.5 iterations
#define POW_ITERS 8
#define TOL2 1.4901161193847656e-6   // (10*1024*eps_fp32)^2, double

// ---------------- scratch (static device globals) ----------------
__device__ float g_q[NB * SS * DKK];
__device__ float g_k[NB * SS * DKK];
__device__ float g_v[NB * SS * DVV];
__device__ float g_attn[NB * SS * SS];
__device__ float g_X[NB * SS * SS];
__device__ float g_X2[NB * SS * SS];
__device__ float g_Xn[NB * SS * SS];
__device__ float g_W[NB * SS * DVV];
__device__ float g_vx[NB * SS];
__device__ float g_vy[NB * SS];
__device__ float g_vz[NB * SS];
__device__ float g_scal[NB * 8];  // slot0 = lam1

#define BM 64
#define BN 64
#define BK 16

#define FLUSH_ACC() do { \
    _Pragma("unroll") \
    for (int _i = 0; _i < 4; _i++) \
        _Pragma("unroll") \
        for (int _j = 0; _j < 4; _j++) { tot[_i][_j] += acc[_i][_j]; acc[_i][_j] = 0.f; } \
} while (0)

// C[m,n] = scale*( sum_e A[m,e]*B[n,e] + bias[n] )  (NT), binned accumulation
__global__ void gemm_nt(const float* __restrict__ A, const float* __restrict__ Bmat,
                        float* __restrict__ C, int M, int N, int E,
                        long sA, long sB, long sC,
                        const float* __restrict__ bias, float scale) {
    __shared__ float As[BK][BM];
    __shared__ float Bs[BK][BN];
    const float* Ab = A + (long)blockIdx.z * sA;
    const float* Bb = Bmat + (long)blockIdx.z * sB;
    float* Cb = C + (long)blockIdx.z * sC;
    const int m0 = blockIdx.y * BM;
    const int n0 = blockIdx.x * BN;
    const int tid = threadIdx.x;
    const int tx = tid & 15;
    const int ty = tid >> 4;
    float acc[4][4] = {};
    float tot[4][4] = {};
    int cc = 0;
    for (int e0 = 0; e0 < E; e0 += BK, cc++) {
        #pragma unroll
        for (int i = 0; i < 4; i++) {
            int idx = tid + i * 256;
            int r = idx / BK;
            int e = idx % BK;
            As[e][r] = Ab[(long)(m0 + r) * E + e0 + e];
            Bs[e][r] = Bb[(long)(n0 + r) * E + e0 + e];
        }
        __syncthreads();
        #pragma unroll
        for (int e = 0; e < BK; e++) {
            float a[4], b[4];
            #pragma unroll
            for (int i = 0; i < 4; i++) a[i] = As[e][ty * 4 + i];
            #pragma unroll
            for (int j = 0; j < 4; j++) b[j] = Bs[e][tx * 4 + j];
            #pragma unroll
            for (int i = 0; i < 4; i++)
                #pragma unroll
                for (int j = 0; j < 4; j++)
                    acc[i][j] += a[i] * b[j];
        }
        __syncthreads();
        if ((cc & 7) == 7) FLUSH_ACC();
    }
    FLUSH_ACC();
    #pragma unroll
    for (int i = 0; i < 4; i++) {
        int m = m0 + ty * 4 + i;
        #pragma unroll
        for (int j = 0; j < 4; j++) {
            int n = n0 + tx * 4 + j;
            float val = tot[i][j];
            if (bias) val += bias[n];
            Cb[(long)m * N + n] = scale * val;
        }
    }
}

// C[m,n] = beta * sum_k A[m,k]*B[k,n]  (+ alpha*L[m,n] if L)   (NN), binned
__global__ void gemm_nn_ep(const float* __restrict__ A, const float* __restrict__ Bmat,
                           const float* __restrict__ L, float* __restrict__ C,
                           int M, int N, int K,
                           long sA, long sB, long sL, long sC,
                           float alpha, float beta) {
    __shared__ float As[BK][BM];
    __shared__ float Bs[BK][BN];
    const float* Ab = A + (long)blockIdx.z * sA;
    const float* Bb = Bmat + (long)blockIdx.z * sB;
    float* Cb = C + (long)blockIdx.z * sC;
    const int m0 = blockIdx.y * BM;
    const int n0 = blockIdx.x * BN;
    const int tid = threadIdx.x;
    const int tx = tid & 15;
    const int ty = tid >> 4;
    float acc[4][4] = {};
    float tot[4][4] = {};
    int cc = 0;
    for (int k0 = 0; k0 < K; k0 += BK, cc++) {
        #pragma unroll
        for (int i = 0; i < 4; i++) {
            int idx = tid + i * 256;
            int r = idx / BK;
            int e = idx % BK;
            As[e][r] = Ab[(long)(m0 + r) * K + k0 + e];
            int kk = idx / BN;
            int nn = idx % BN;
            Bs[kk][nn] = Bb[(long)(k0 + kk) * N + n0 + nn];
        }
        __syncthreads();
        #pragma unroll
        for (int e = 0; e < BK; e++) {
            float a[4], b[4];
            #pragma unroll
            for (int i = 0; i < 4; i++) a[i] = As[e][ty * 4 + i];
            #pragma unroll
            for (int j = 0; j < 4; j++) b[j] = Bs[e][tx * 4 + j];
            #pragma unroll
            for (int i = 0; i < 4; i++)
                #pragma unroll
                for (int j = 0; j < 4; j++)
                    acc[i][j] += a[i] * b[j];
        }
        __syncthreads();
        if ((cc & 7) == 7) FLUSH_ACC();
    }
    FLUSH_ACC();
    #pragma unroll
    for (int i = 0; i < 4; i++) {
        int m = m0 + ty * 4 + i;
        #pragma unroll
        for (int j = 0; j < 4; j++) {
            int n = n0 + tx * 4 + j;
            float val = beta * tot[i][j];
            if (L) val += alpha * L[(long)blockIdx.z * sL + (long)m * N + n];
            Cb[(long)m * N + n] = val;
        }
    }
}

// X0[i,j] = (float)(( sum_m A[m,i]A[m,j] (fp64) - tau*delta_ij ) / (1.3*lam1))
// NO deflation: the uniform mode saturates to +1 inside the sign iteration.
__global__ void syrk_buildX0_f64(const float* __restrict__ A,
                                 const float* __restrict__ scal, float* __restrict__ X) {
    __shared__ float As[BK][BM];
    __shared__ float Bs[BK][BN];
    const int b = blockIdx.z;
    const float* Ab = A + (long)b * SS * SS;
    float* Xb = X + (long)b * SS * SS;
    const int i0 = blockIdx.y * BM;
    const int j0 = blockIdx.x * BN;
    const int tid = threadIdx.x;
    const int tx = tid & 15;
    const int ty = tid >> 4;
    double acc[4][4] = {};
    for (int k0 = 0; k0 < SS; k0 += BK) {
        #pragma unroll
        for (int t = 0; t < 4; t++) {
            int idx = tid + t * 256;
            int kk = idx / BN;
            int rr = idx % BN;
            As[kk][rr] = Ab[(long)(k0 + kk) * SS + i0 + rr];
            Bs[kk][rr] = Ab[(long)(k0 + kk) * SS + j0 + rr];
        }
        __syncthreads();
        #pragma unroll
        for (int e = 0; e < BK; e++) {
            float a[4], bb[4];
            #pragma unroll
            for (int i = 0; i < 4; i++) a[i] = As[e][ty * 4 + i];
            #pragma unroll
            for (int j = 0; j < 4; j++) bb[j] = Bs[e][tx * 4 + j];
            #pragma unroll
            for (int i = 0; i < 4; i++)
                #pragma unroll
                for (int j = 0; j < 4; j++)
                    acc[i][j] += (double)a[i] * (double)bb[j];
        }
        __syncthreads();
    }
    const double lam1 = (double)scal[b * 8 + 0];
    const double tau  = TOL2 * lam1;
    const double inv_s = 1.0 / (1.3 * lam1);
    #pragma unroll
    for (int i = 0; i < 4; i++) {
        int ii = i0 + ty * 4 + i;
        #pragma unroll
        for (int j = 0; j < 4; j++) {
            int jj = j0 + tx * 4 + j;
            double val = acc[i][j];
            if (ii == jj) val -= tau;
            Xb[(long)ii * SS + jj] = (float)(val * inv_s);
        }
    }
}

// In-place row softmax, one block per row of 1024
__global__ void softmax_rows(float* __restrict__ A) {
    float* row = A + (long)blockIdx.x * SS;
    const int t = threadIdx.x;
    __shared__ float red[256];
    float v[4];
    float mx = -1e30f;
    #pragma unroll
    for (int i = 0; i < 4; i++) { v[i] = row[t + i * 256]; mx = fmaxf(mx, v[i]); }
    red[t] = mx; __syncthreads();
    for (int s = 128; s > 0; s >>= 1) { if (t < s) red[t] = fmaxf(red[t], red[t + s]); __syncthreads(); }
    mx = red[0]; __syncthreads();
    float sum = 0.f;
    #pragma unroll
    for (int i = 0; i < 4; i++) { v[i] = expf(v[i] - mx); sum += v[i]; }
    red[t] = sum; __syncthreads();
    for (int s = 128; s > 0; s >>= 1) { if (t < s) red[t] += red[t + s]; __syncthreads(); }
    const float inv = 1.f / red[0];
    #pragma unroll
    for (int i = 0; i < 4; i++) row[t + i * 256] = v[i] * inv;
}

// ---------------- small vector kernels ----------------
__global__ void k_fill(float* x, float val) {
    int i = blockIdx.x * blockDim.x + threadIdx.x;
    if (i < NB * SS) x[i] = val;
}
// z[b,:] = M[b] x[b,:]  : warp per row
__global__ void k_matvec(const float* __restrict__ M, const float* __restrict__ x,
                         float* __restrict__ y) {
    int b = blockIdx.y;
    int wid = threadIdx.x >> 5;
    int lane = threadIdx.x & 31;
    int row = blockIdx.x * 8 + wid;
    const float* Mb = M + (long)b * SS * SS + (long)row * SS;
    const float* xb = x + b * SS;
    float s = 0.f;
    for (int j = lane; j < SS; j += 32) s += Mb[j] * xb[j];
    #pragma unroll
    for (int o = 16; o > 0; o >>= 1) s += __shfl_down_sync(0xffffffffu, s, o);
    if (lane == 0) y[b * SS + row] = s;
}
// y[b,j] = sum_m A[b,m,j] z[b,m]
__global__ void k_matvecT(const float* __restrict__ A, const float* __restrict__ z,
                          float* __restrict__ y) {
    __shared__ float zs[SS];
    int b = blockIdx.y;
    int j = blockIdx.x * 256 + threadIdx.x;
    const float* Ab = A + (long)b * SS * SS;
    for (int m = threadIdx.x; m < SS; m += 256) zs[m] = z[b * SS + m];
    __syncthreads();
    float s = 0.f;
    for (int m = 0; m < SS; m++) s += Ab[(long)m * SS + j] * zs[m];
    y[b * SS + j] = s;
}
// x = y/||y||, store ||y|| in scal[b*8+slot]
__global__ void k_normalize(const float* __restrict__ y, float* __restrict__ x,
                            float* __restrict__ scal, int slot) {
    int b = blockIdx.x, t = threadIdx.x;
    __shared__ float red[256];
    const float* yb = y + b * SS;
    float v[4]; float ss = 0.f;
    #pragma unroll
    for (int i = 0; i < 4; i++) { v[i] = yb[t + i * 256]; ss += v[i] * v[i]; }
    red[t] = ss; __syncthreads();
    for (int s = 128; s > 0; s >>= 1) { if (t < s) red[t] += red[t + s]; __syncthreads(); }
    float nrm = sqrtf(red[0]);
    if (t == 0) scal[b * 8 + slot] = nrm;
    float inv = 1.f / nrm;
    #pragma unroll
    for (int i = 0; i < 4; i++) x[b * SS + t + i * 256] = v[i] * inv;
}
// W = 0.5*(V + Y)
__global__ void k_combine2(const float* __restrict__ V, const float* __restrict__ Y,
                           float* __restrict__ W) {
    long idx = (long)blockIdx.x * blockDim.x + threadIdx.x;
    if (idx >= (long)NB * SS * DVV) return;
    W[idx] = 0.5f * (V[idx] + Y[idx]);
}

extern "C" void kernel_launch(void* const* d_in, const int* in_sizes, int n_in,
                              void* d_out, int out_size) {
    const float* query_in = (const float*)d_in[0];
    const float* key_in   = (const float*)d_in[1];
    const float* value_in = (const float*)d_in[2];
    const float* Wq = (const float*)d_in[3];
    const float* bq = (const float*)d_in[4];
    const float* Wk = (const float*)d_in[5];
    const float* bk = (const float*)d_in[6];
    const float* Wv = (const float*)d_in[7];
    const float* bv = (const float*)d_in[8];
    float* out = (float*)d_out;

    float *q, *k, *v, *attn, *X, *X2, *Xn, *W, *vx, *vy, *vz, *scal;
    cudaGetSymbolAddress((void**)&q, g_q);
    cudaGetSymbolAddress((void**)&k, g_k);
    cudaGetSymbolAddress((void**)&v, g_v);
    cudaGetSymbolAddress((void**)&attn, g_attn);
    cudaGetSymbolAddress((void**)&X, g_X);
    cudaGetSymbolAddress((void**)&X2, g_X2);
    cudaGetSymbolAddress((void**)&Xn, g_Xn);
    cudaGetSymbolAddress((void**)&W, g_W);
    cudaGetSymbolAddress((void**)&vx, g_vx);
    cudaGetSymbolAddress((void**)&vy, g_vy);
    cudaGetSymbolAddress((void**)&vz, g_vz);
    cudaGetSymbolAddress((void**)&scal, g_scal);

    const float scaling = 0.21022410381342863f;  // 512^-0.25
    const long SSS = (long)SS * SS;
    const long SDV = (long)SS * DVV;

    // ---- projections ----
    {
        dim3 grid(DKK / BN, (NB * SS) / BM, 1);
        gemm_nt<<<grid, 256>>>(query_in, Wq, q, NB * SS, DKK, EE, 0, 0, 0, bq, scaling);
        gemm_nt<<<grid, 256>>>(key_in,   Wk, k, NB * SS, DKK, EE, 0, 0, 0, bk, scaling);
        gemm_nt<<<grid, 256>>>(value_in, Wv, v, NB * SS, DVV, EE, 0, 0, 0, bv, 1.0f);
    }
    // ---- A = softmax(q k^T) ----
    {
        dim3 grid(SS / BN, SS / BM, NB);
        gemm_nt<<<grid, 256>>>(q, k, attn, SS, SS, DKK,
                               (long)SS * DKK, (long)SS * DKK, SSS, nullptr, 1.0f);
    }
    softmax_rows<<<NB * SS, 256>>>(attn);

    // ---- power iteration for lam1 of G = A^T A (matvec-based; only lam1 needed) ----
    k_fill<<<(NB * SS + 255) / 256, 256>>>(vx, 0.03125f);
    for (int it = 0; it < POW_ITERS; it++) {
        k_matvec<<<dim3(SS / 8, NB), 256>>>(attn, vx, vz);    // vz = A vx
        k_matvecT<<<dim3(SS / 256, NB), 256>>>(attn, vz, vy); // vy = A^T vz
        k_normalize<<<NB, 256>>>(vy, vx, scal, 0);            // slot0 -> lam1
    }

    // ---- X0 = (A^T A - tau I) / (1.3 lam1), fp64 fused. No deflation. ----
    {
        dim3 grid(SS / BN, SS / BM, NB);
        syrk_buildX0_f64<<<grid, 256>>>(attn, scal, X);
    }

    // ---- Over-relaxed Newton-Schulz sign: X <- a X - (a-1) X^3 ----
    float* Xa = X;
    float* Xb = Xn;
    dim3 gridNS(SS / BN, SS / BM, NB);
    for (int it = 0; it < NS_GROW + NS_POLISH; it++) {
        float a = (it < NS_GROW) ? 1.9f : 1.5f;
        gemm_nn_ep<<<gridNS, 256>>>(Xa, Xa, nullptr, X2, SS, SS, SS,
                                    SSS, SSS, 0, SSS, 0.f, 1.f);
        gemm_nn_ep<<<gridNS, 256>>>(X2, Xa, Xa, Xb, SS, SS, SS,
                                    SSS, SSS, SSS, SSS, a, -(a - 1.0f));
        float* t = Xa; Xa = Xb; Xb = t;
    }

    // ---- Y = X V  (into X2) ----
    {
        dim3 grid(DVV / BN, SS / BM, NB);
        gemm_nn_ep<<<grid, 256>>>(Xa, v, nullptr, X2, SS, DVV, SS,
                                  SSS, SDV, 0, SDV, 0.f, 1.f);
    }
    // ---- W = 0.5 (V + Y) ----
    {
        long total = (long)NB * SS * DVV;
        k_combine2<<<(unsigned)((total + 255) / 256), 256>>>(v, X2, W);
    }
    // ---- out = A W ----
    {
        dim3 grid(DVV / BN, SS / BM, NB);
        gemm_nn_ep<<<grid, 256>>>(attn, W, nullptr, out, SS, DVV, SS,
                                  SSS, SDV, 0, SDV, 0.f, 1.f);
    }
}

// round 13
// speedup vs baseline: 1.6356x; 1.6356x over previous
#include <cuda_runtime.h>
#include <math.h>

#define NB 8
#define SS 1024
#define EE 1024
#define DKK 512
#define DVV 512

#define NS_GROW 26      // a = 1.9 iterations
#define NS_POLISH 6     // a = 1.5 iterations
#define POW_ITERS 8
#define TOL2 1.4901161193847656e-6   // (10*1024*eps_fp32)^2, double

#define NT 16           // 1024/64 tile grid per dim
#define NPAIRS 136      // NT*(NT+1)/2 upper-triangle blocks

// ---------------- scratch (static device globals) ----------------
__device__ float g_q[NB * SS * DKK];
__device__ float g_k[NB * SS * DKK];
__device__ float g_v[NB * SS * DVV];
__device__ float g_attn[NB * SS * SS];
__device__ float g_X[NB * SS * SS];
__device__ float g_X2[NB * SS * SS];
__device__ float g_Xn[NB * SS * SS];
__device__ float g_W[NB * SS * DVV];
__device__ float g_vx[NB * SS];
__device__ float g_vy[NB * SS];
__device__ float g_vz[NB * SS];
__device__ float g_scal[NB * 8];  // slot0 = lam1

#define BM 64
#define BN 64
#define BK 16

#define FLUSH_ACC() do { \
    _Pragma("unroll") \
    for (int _i = 0; _i < 4; _i++) \
        _Pragma("unroll") \
        for (int _j = 0; _j < 4; _j++) { tot[_i][_j] += acc[_i][_j]; acc[_i][_j] = 0.f; } \
} while (0)

__device__ __forceinline__ void decode_tri(int t, int& bi, int& bj) {
    int rem = t;
    int i = 0;
    while (rem >= NT - i) { rem -= NT - i; i++; }
    bi = i;
    bj = i + rem;
}

// C[m,n] = scale*( sum_e A[m,e]*B[n,e] + bias[n] )  (NT), binned accumulation
__global__ void gemm_nt(const float* __restrict__ A, const float* __restrict__ Bmat,
                        float* __restrict__ C, int M, int N, int E,
                        long sA, long sB, long sC,
                        const float* __restrict__ bias, float scale) {
    __shared__ float As[BK][BM];
    __shared__ float Bs[BK][BN];
    const float* Ab = A + (long)blockIdx.z * sA;
    const float* Bb = Bmat + (long)blockIdx.z * sB;
    float* Cb = C + (long)blockIdx.z * sC;
    const int m0 = blockIdx.y * BM;
    const int n0 = blockIdx.x * BN;
    const int tid = threadIdx.x;
    const int tx = tid & 15;
    const int ty = tid >> 4;
    float acc[4][4] = {};
    float tot[4][4] = {};
    int cc = 0;
    for (int e0 = 0; e0 < E; e0 += BK, cc++) {
        #pragma unroll
        for (int i = 0; i < 4; i++) {
            int idx = tid + i * 256;
            int r = idx / BK;
            int e = idx % BK;
            As[e][r] = Ab[(long)(m0 + r) * E + e0 + e];
            Bs[e][r] = Bb[(long)(n0 + r) * E + e0 + e];
        }
        __syncthreads();
        #pragma unroll
        for (int e = 0; e < BK; e++) {
            float a[4], b[4];
            #pragma unroll
            for (int i = 0; i < 4; i++) a[i] = As[e][ty * 4 + i];
            #pragma unroll
            for (int j = 0; j < 4; j++) b[j] = Bs[e][tx * 4 + j];
            #pragma unroll
            for (int i = 0; i < 4; i++)
                #pragma unroll
                for (int j = 0; j < 4; j++)
                    acc[i][j] += a[i] * b[j];
        }
        __syncthreads();
        if ((cc & 7) == 7) FLUSH_ACC();
    }
    FLUSH_ACC();
    #pragma unroll
    for (int i = 0; i < 4; i++) {
        int m = m0 + ty * 4 + i;
        #pragma unroll
        for (int j = 0; j < 4; j++) {
            int n = n0 + tx * 4 + j;
            float val = tot[i][j];
            if (bias) val += bias[n];
            Cb[(long)m * N + n] = scale * val;
        }
    }
}

// C[m,n] = beta * sum_k A[m,k]*B[k,n]  (+ alpha*L[m,n] if L)   (NN), binned
__global__ void gemm_nn_ep(const float* __restrict__ A, const float* __restrict__ Bmat,
                           const float* __restrict__ L, float* __restrict__ C,
                           int M, int N, int K,
                           long sA, long sB, long sL, long sC,
                           float alpha, float beta) {
    __shared__ float As[BK][BM];
    __shared__ float Bs[BK][BN];
    const float* Ab = A + (long)blockIdx.z * sA;
    const float* Bb = Bmat + (long)blockIdx.z * sB;
    float* Cb = C + (long)blockIdx.z * sC;
    const int m0 = blockIdx.y * BM;
    const int n0 = blockIdx.x * BN;
    const int tid = threadIdx.x;
    const int tx = tid & 15;
    const int ty = tid >> 4;
    float acc[4][4] = {};
    float tot[4][4] = {};
    int cc = 0;
    for (int k0 = 0; k0 < K; k0 += BK, cc++) {
        #pragma unroll
        for (int i = 0; i < 4; i++) {
            int idx = tid + i * 256;
            int r = idx / BK;
            int e = idx % BK;
            As[e][r] = Ab[(long)(m0 + r) * K + k0 + e];
            int kk = idx / BN;
            int nn = idx % BN;
            Bs[kk][nn] = Bb[(long)(k0 + kk) * N + n0 + nn];
        }
        __syncthreads();
        #pragma unroll
        for (int e = 0; e < BK; e++) {
            float a[4], b[4];
            #pragma unroll
            for (int i = 0; i < 4; i++) a[i] = As[e][ty * 4 + i];
            #pragma unroll
            for (int j = 0; j < 4; j++) b[j] = Bs[e][tx * 4 + j];
            #pragma unroll
            for (int i = 0; i < 4; i++)
                #pragma unroll
                for (int j = 0; j < 4; j++)
                    acc[i][j] += a[i] * b[j];
        }
        __syncthreads();
        if ((cc & 7) == 7) FLUSH_ACC();
    }
    FLUSH_ACC();
    #pragma unroll
    for (int i = 0; i < 4; i++) {
        int m = m0 + ty * 4 + i;
        #pragma unroll
        for (int j = 0; j < 4; j++) {
            int n = n0 + tx * 4 + j;
            float val = beta * tot[i][j];
            if (L) val += alpha * L[(long)blockIdx.z * sL + (long)m * N + n];
            Cb[(long)m * N + n] = val;
        }
    }
}

// Symmetric-output NN gemm over batched SSxSS matrices.
// C = beta*(A@B) + alpha*L (L batched symmetric or null). Result known symmetric:
// computes only upper-triangle tile (bi<=bj) and mirror-writes the transpose.
__global__ void gemm_nn_sym(const float* __restrict__ A, const float* __restrict__ Bmat,
                            const float* __restrict__ L, float* __restrict__ C,
                            float alpha, float beta) {
    __shared__ float As[BK][BM];
    __shared__ float Bs[BK][BN];
    const long SSL = (long)SS * SS;
    const float* Ab = A + (long)blockIdx.z * SSL;
    const float* Bb = Bmat + (long)blockIdx.z * SSL;
    const float* Lb = L ? (L + (long)blockIdx.z * SSL) : (const float*)0;  // FIX: batch offset
    float* Cb = C + (long)blockIdx.z * SSL;
    int bi, bj;
    decode_tri(blockIdx.x, bi, bj);
    const int m0 = bi * BM;
    const int n0 = bj * BN;
    const int tid = threadIdx.x;
    const int tx = tid & 15;
    const int ty = tid >> 4;
    float acc[4][4] = {};
    float tot[4][4] = {};
    int cc = 0;
    for (int k0 = 0; k0 < SS; k0 += BK, cc++) {
        #pragma unroll
        for (int i = 0; i < 4; i++) {
            int idx = tid + i * 256;
            int r = idx / BK;
            int e = idx % BK;
            As[e][r] = Ab[(long)(m0 + r) * SS + k0 + e];
            int kk = idx / BN;
            int nn = idx % BN;
            Bs[kk][nn] = Bb[(long)(k0 + kk) * SS + n0 + nn];
        }
        __syncthreads();
        #pragma unroll
        for (int e = 0; e < BK; e++) {
            float a[4], b[4];
            #pragma unroll
            for (int i = 0; i < 4; i++) a[i] = As[e][ty * 4 + i];
            #pragma unroll
            for (int j = 0; j < 4; j++) b[j] = Bs[e][tx * 4 + j];
            #pragma unroll
            for (int i = 0; i < 4; i++)
                #pragma unroll
                for (int j = 0; j < 4; j++)
                    acc[i][j] += a[i] * b[j];
        }
        __syncthreads();
        if ((cc & 7) == 7) FLUSH_ACC();
    }
    FLUSH_ACC();
    const bool mirror = (bi != bj);
    #pragma unroll
    for (int i = 0; i < 4; i++) {
        int m = m0 + ty * 4 + i;
        #pragma unroll
        for (int j = 0; j < 4; j++) {
            int n = n0 + tx * 4 + j;
            float val = beta * tot[i][j];
            if (Lb) val += alpha * Lb[(long)m * SS + n];  // L symmetric per batch
            Cb[(long)m * SS + n] = val;
            if (mirror) Cb[(long)n * SS + m] = val;
        }
    }
}

// X0[i,j] = (float)(( sum_m A[m,i]A[m,j] (fp64) - tau*delta_ij ) / (1.3*lam1))
// Upper-triangle blocks only + mirror write (output symmetric by construction).
__global__ void syrk_buildX0_f64(const float* __restrict__ A,
                                 const float* __restrict__ scal, float* __restrict__ X) {
    __shared__ float As[BK][BM];
    __shared__ float Bs[BK][BN];
    const int b = blockIdx.z;
    const float* Ab = A + (long)b * SS * SS;
    float* Xb = X + (long)b * SS * SS;
    int bi, bj;
    decode_tri(blockIdx.x, bi, bj);
    const int i0 = bi * BM;
    const int j0 = bj * BN;
    const int tid = threadIdx.x;
    const int tx = tid & 15;
    const int ty = tid >> 4;
    double acc[4][4] = {};
    for (int k0 = 0; k0 < SS; k0 += BK) {
        #pragma unroll
        for (int t = 0; t < 4; t++) {
            int idx = tid + t * 256;
            int kk = idx / BN;
            int rr = idx % BN;
            As[kk][rr] = Ab[(long)(k0 + kk) * SS + i0 + rr];
            Bs[kk][rr] = Ab[(long)(k0 + kk) * SS + j0 + rr];
        }
        __syncthreads();
        #pragma unroll
        for (int e = 0; e < BK; e++) {
            float a[4], bb[4];
            #pragma unroll
            for (int i = 0; i < 4; i++) a[i] = As[e][ty * 4 + i];
            #pragma unroll
            for (int j = 0; j < 4; j++) bb[j] = Bs[e][tx * 4 + j];
            #pragma unroll
            for (int i = 0; i < 4; i++)
                #pragma unroll
                for (int j = 0; j < 4; j++)
                    acc[i][j] += (double)a[i] * (double)bb[j];
        }
        __syncthreads();
    }
    const double lam1 = (double)scal[b * 8 + 0];
    const double tau  = TOL2 * lam1;
    const double inv_s = 1.0 / (1.3 * lam1);
    const bool mirror = (bi != bj);
    #pragma unroll
    for (int i = 0; i < 4; i++) {
        int ii = i0 + ty * 4 + i;
        #pragma unroll
        for (int j = 0; j < 4; j++) {
            int jj = j0 + tx * 4 + j;
            double val = acc[i][j];
            if (ii == jj) val -= tau;
            float f = (float)(val * inv_s);
            Xb[(long)ii * SS + jj] = f;
            if (mirror) Xb[(long)jj * SS + ii] = f;
        }
    }
}

// In-place row softmax, one block per row of 1024
__global__ void softmax_rows(float* __restrict__ A) {
    float* row = A + (long)blockIdx.x * SS;
    const int t = threadIdx.x;
    __shared__ float red[256];
    float v[4];
    float mx = -1e30f;
    #pragma unroll
    for (int i = 0; i < 4; i++) { v[i] = row[t + i * 256]; mx = fmaxf(mx, v[i]); }
    red[t] = mx; __syncthreads();
    for (int s = 128; s > 0; s >>= 1) { if (t < s) red[t] = fmaxf(red[t], red[t + s]); __syncthreads(); }
    mx = red[0]; __syncthreads();
    float sum = 0.f;
    #pragma unroll
    for (int i = 0; i < 4; i++) { v[i] = expf(v[i] - mx); sum += v[i]; }
    red[t] = sum; __syncthreads();
    for (int s = 128; s > 0; s >>= 1) { if (t < s) red[t] += red[t + s]; __syncthreads(); }
    const float inv = 1.f / red[0];
    #pragma unroll
    for (int i = 0; i < 4; i++) row[t + i * 256] = v[i] * inv;
}

// ---------------- small vector kernels ----------------
__global__ void k_fill(float* x, float val) {
    int i = blockIdx.x * blockDim.x + threadIdx.x;
    if (i < NB * SS) x[i] = val;
}
// z[b,:] = M[b] x[b,:]  : warp per row
__global__ void k_matvec(const float* __restrict__ M, const float* __restrict__ x,
                         float* __restrict__ y) {
    int b = blockIdx.y;
    int wid = threadIdx.x >> 5;
    int lane = threadIdx.x & 31;
    int row = blockIdx.x * 8 + wid;
    const float* Mb = M + (long)b * SS * SS + (long)row * SS;
    const float* xb = x + b * SS;
    float s = 0.f;
    for (int j = lane; j < SS; j += 32) s += Mb[j] * xb[j];
    #pragma unroll
    for (int o = 16; o > 0; o >>= 1) s += __shfl_down_sync(0xffffffffu, s, o);
    if (lane == 0) y[b * SS + row] = s;
}
// y[b,j] = sum_m A[b,m,j] z[b,m]
__global__ void k_matvecT(const float* __restrict__ A, const float* __restrict__ z,
                          float* __restrict__ y) {
    __shared__ float zs[SS];
    int b = blockIdx.y;
    int j = blockIdx.x * 256 + threadIdx.x;
    const float* Ab = A + (long)b * SS * SS;
    for (int m = threadIdx.x; m < SS; m += 256) zs[m] = z[b * SS + m];
    __syncthreads();
    float s = 0.f;
    for (int m = 0; m < SS; m++) s += Ab[(long)m * SS + j] * zs[m];
    y[b * SS + j] = s;
}
// x = y/||y||, store ||y|| in scal[b*8+slot]
__global__ void k_normalize(const float* __restrict__ y, float* __restrict__ x,
                            float* __restrict__ scal, int slot) {
    int b = blockIdx.x, t = threadIdx.x;
    __shared__ float red[256];
    const float* yb = y + b * SS;
    float v[4]; float ss = 0.f;
    #pragma unroll
    for (int i = 0; i < 4; i++) { v[i] = yb[t + i * 256]; ss += v[i] * v[i]; }
    red[t] = ss; __syncthreads();
    for (int s = 128; s > 0; s >>= 1) { if (t < s) red[t] += red[t + s]; __syncthreads(); }
    float nrm = sqrtf(red[0]);
    if (t == 0) scal[b * 8 + slot] = nrm;
    float inv = 1.f / nrm;
    #pragma unroll
    for (int i = 0; i < 4; i++) x[b * SS + t + i * 256] = v[i] * inv;
}
// W = 0.5*(V + Y)
__global__ void k_combine2(const float* __restrict__ V, const float* __restrict__ Y,
                           float* __restrict__ W) {
    long idx = (long)blockIdx.x * blockDim.x + threadIdx.x;
    if (idx >= (long)NB * SS * DVV) return;
    W[idx] = 0.5f * (V[idx] + Y[idx]);
}

extern "C" void kernel_launch(void* const* d_in, const int* in_sizes, int n_in,
                              void* d_out, int out_size) {
    const float* query_in = (const float*)d_in[0];
    const float* key_in   = (const float*)d_in[1];
    const float* value_in = (const float*)d_in[2];
    const float* Wq = (const float*)d_in[3];
    const float* bq = (const float*)d_in[4];
    const float* Wk = (const float*)d_in[5];
    const float* bk = (const float*)d_in[6];
    const float* Wv = (const float*)d_in[7];
    const float* bv = (const float*)d_in[8];
    float* out = (float*)d_out;

    float *q, *k, *v, *attn, *X, *X2, *Xn, *W, *vx, *vy, *vz, *scal;
    cudaGetSymbolAddress((void**)&q, g_q);
    cudaGetSymbolAddress((void**)&k, g_k);
    cudaGetSymbolAddress((void**)&v, g_v);
    cudaGetSymbolAddress((void**)&attn, g_attn);
    cudaGetSymbolAddress((void**)&X, g_X);
    cudaGetSymbolAddress((void**)&X2, g_X2);
    cudaGetSymbolAddress((void**)&Xn, g_Xn);
    cudaGetSymbolAddress((void**)&W, g_W);
    cudaGetSymbolAddress((void**)&vx, g_vx);
    cudaGetSymbolAddress((void**)&vy, g_vy);
    cudaGetSymbolAddress((void**)&vz, g_vz);
    cudaGetSymbolAddress((void**)&scal, g_scal);

    const float scaling = 0.21022410381342863f;  // 512^-0.25
    const long SSS = (long)SS * SS;
    const long SDV = (long)SS * DVV;

    // ---- projections ----
    {
        dim3 grid(DKK / BN, (NB * SS) / BM, 1);
        gemm_nt<<<grid, 256>>>(query_in, Wq, q, NB * SS, DKK, EE, 0, 0, 0, bq, scaling);
        gemm_nt<<<grid, 256>>>(key_in,   Wk, k, NB * SS, DKK, EE, 0, 0, 0, bk, scaling);
        gemm_nt<<<grid, 256>>>(value_in, Wv, v, NB * SS, DVV, EE, 0, 0, 0, bv, 1.0f);
    }
    // ---- A = softmax(q k^T) ----
    {
        dim3 grid(SS / BN, SS / BM, NB);
        gemm_nt<<<grid, 256>>>(q, k, attn, SS, SS, DKK,
                               (long)SS * DKK, (long)SS * DKK, SSS, nullptr, 1.0f);
    }
    softmax_rows<<<NB * SS, 256>>>(attn);

    // ---- power iteration for lam1 of G = A^T A (matvec-based; only lam1 needed) ----
    k_fill<<<(NB * SS + 255) / 256, 256>>>(vx, 0.03125f);
    for (int it = 0; it < POW_ITERS; it++) {
        k_matvec<<<dim3(SS / 8, NB), 256>>>(attn, vx, vz);    // vz = A vx
        k_matvecT<<<dim3(SS / 256, NB), 256>>>(attn, vz, vy); // vy = A^T vz
        k_normalize<<<NB, 256>>>(vy, vx, scal, 0);            // slot0 -> lam1
    }

    // ---- X0 = (A^T A - tau I) / (1.3 lam1), fp64 fused, upper-tri + mirror ----
    {
        dim3 grid(NPAIRS, 1, NB);
        syrk_buildX0_f64<<<grid, 256>>>(attn, scal, X);
    }

    // ---- Over-relaxed Newton-Schulz sign: X <- a X - (a-1) X^3 ----
    // All iterates are polynomials in X0 => symmetric => symmetric-half GEMMs.
    float* Xa = X;
    float* Xb = Xn;
    dim3 gridNS(NPAIRS, 1, NB);
    for (int it = 0; it < NS_GROW + NS_POLISH; it++) {
        float a = (it < NS_GROW) ? 1.9f : 1.5f;
        gemm_nn_sym<<<gridNS, 256>>>(Xa, Xa, nullptr, X2, 0.f, 1.f);
        gemm_nn_sym<<<gridNS, 256>>>(X2, Xa, Xa, Xb, a, -(a - 1.0f));
        float* t = Xa; Xa = Xb; Xb = t;
    }

    // ---- Y = X V  (into X2) ----
    {
        dim3 grid(DVV / BN, SS / BM, NB);
        gemm_nn_ep<<<grid, 256>>>(Xa, v, nullptr, X2, SS, DVV, SS,
                                  SSS, SDV, 0, SDV, 0.f, 1.f);
    }
    // ---- W = 0.5 (V + Y) ----
    {
        long total = (long)NB * SS * DVV;
        k_combine2<<<(unsigned)((total + 255) / 256), 256>>>(v, X2, W);
    }
    // ---- out = A W ----
    {
        dim3 grid(DVV / BN, SS / BM, NB);
        gemm_nn_ep<<<grid, 256>>>(attn, W, nullptr, out, SS, DVV, SS,
                                  SSS, SDV, 0, SDV, 0.f, 1.f);
    }
}

// round 14
// speedup vs baseline: 2.0269x; 1.2393x over previous
#include <cuda_runtime.h>
#include <math.h>

#define NB 8
#define SS 1024
#define EE 1024
#define DKK 512
#define DVV 512

#define NS_GROW 26      // a = 1.9 iterations
#define NS_POLISH 6     // a = 1.5 iterations
#define POW_ITERS 8
#define TOL2 1.4901161193847656e-6   // (10*1024*eps_fp32)^2, double

#define NT 16           // 64-px tile grid (X0 build)
#define NPAIRS 136
#define NT8 8           // 128-px tile grid (NS loop)
#define NP8 36          // NT8*(NT8+1)/2

// ---------------- scratch (static device globals) ----------------
__device__ float g_q[NB * SS * DKK];
__device__ float g_k[NB * SS * DKK];
__device__ float g_v[NB * SS * DVV];
__device__ float g_attn[NB * SS * SS];
__device__ float g_X[NB * SS * SS];
__device__ float g_X2[NB * SS * SS];
__device__ float g_Xn[NB * SS * SS];
__device__ float g_W[NB * SS * DVV];
__device__ float g_vx[NB * SS];
__device__ float g_vy[NB * SS];
__device__ float g_vz[NB * SS];
__device__ float g_scal[NB * 8];  // slot0 = lam1

#define BM 64
#define BN 64
#define BK 16

#define FLUSH_ACC() do { \
    _Pragma("unroll") \
    for (int _i = 0; _i < 4; _i++) \
        _Pragma("unroll") \
        for (int _j = 0; _j < 4; _j++) { tot[_i][_j] += acc[_i][_j]; acc[_i][_j] = 0.f; } \
} while (0)

#define FLUSH_ACC8() do { \
    _Pragma("unroll") \
    for (int _i = 0; _i < 8; _i++) \
        _Pragma("unroll") \
        for (int _j = 0; _j < 8; _j++) { tot[_i][_j] += acc[_i][_j]; acc[_i][_j] = 0.f; } \
} while (0)

__device__ __forceinline__ void decode_tri(int t, int& bi, int& bj) {
    int rem = t;
    int i = 0;
    while (rem >= NT - i) { rem -= NT - i; i++; }
    bi = i;
    bj = i + rem;
}
__device__ __forceinline__ void decode_tri8(int t, int& bi, int& bj) {
    int rem = t;
    int i = 0;
    while (rem >= NT8 - i) { rem -= NT8 - i; i++; }
    bi = i;
    bj = i + rem;
}

// C[m,n] = scale*( sum_e A[m,e]*B[n,e] + bias[n] )  (NT), binned accumulation
__global__ void gemm_nt(const float* __restrict__ A, const float* __restrict__ Bmat,
                        float* __restrict__ C, int M, int N, int E,
                        long sA, long sB, long sC,
                        const float* __restrict__ bias, float scale) {
    __shared__ float As[BK][BM];
    __shared__ float Bs[BK][BN];
    const float* Ab = A + (long)blockIdx.z * sA;
    const float* Bb = Bmat + (long)blockIdx.z * sB;
    float* Cb = C + (long)blockIdx.z * sC;
    const int m0 = blockIdx.y * BM;
    const int n0 = blockIdx.x * BN;
    const int tid = threadIdx.x;
    const int tx = tid & 15;
    const int ty = tid >> 4;
    float acc[4][4] = {};
    float tot[4][4] = {};
    int cc = 0;
    for (int e0 = 0; e0 < E; e0 += BK, cc++) {
        #pragma unroll
        for (int i = 0; i < 4; i++) {
            int idx = tid + i * 256;
            int r = idx / BK;
            int e = idx % BK;
            As[e][r] = Ab[(long)(m0 + r) * E + e0 + e];
            Bs[e][r] = Bb[(long)(n0 + r) * E + e0 + e];
        }
        __syncthreads();
        #pragma unroll
        for (int e = 0; e < BK; e++) {
            float a[4], b[4];
            #pragma unroll
            for (int i = 0; i < 4; i++) a[i] = As[e][ty * 4 + i];
            #pragma unroll
            for (int j = 0; j < 4; j++) b[j] = Bs[e][tx * 4 + j];
            #pragma unroll
            for (int i = 0; i < 4; i++)
                #pragma unroll
                for (int j = 0; j < 4; j++)
                    acc[i][j] += a[i] * b[j];
        }
        __syncthreads();
        if ((cc & 7) == 7) FLUSH_ACC();
    }
    FLUSH_ACC();
    #pragma unroll
    for (int i = 0; i < 4; i++) {
        int m = m0 + ty * 4 + i;
        #pragma unroll
        for (int j = 0; j < 4; j++) {
            int n = n0 + tx * 4 + j;
            float val = tot[i][j];
            if (bias) val += bias[n];
            Cb[(long)m * N + n] = scale * val;
        }
    }
}

// C[m,n] = beta * sum_k A[m,k]*B[k,n]  (+ alpha*L[m,n] if L)   (NN), binned
__global__ void gemm_nn_ep(const float* __restrict__ A, const float* __restrict__ Bmat,
                           const float* __restrict__ L, float* __restrict__ C,
                           int M, int N, int K,
                           long sA, long sB, long sL, long sC,
                           float alpha, float beta) {
    __shared__ float As[BK][BM];
    __shared__ float Bs[BK][BN];
    const float* Ab = A + (long)blockIdx.z * sA;
    const float* Bb = Bmat + (long)blockIdx.z * sB;
    float* Cb = C + (long)blockIdx.z * sC;
    const int m0 = blockIdx.y * BM;
    const int n0 = blockIdx.x * BN;
    const int tid = threadIdx.x;
    const int tx = tid & 15;
    const int ty = tid >> 4;
    float acc[4][4] = {};
    float tot[4][4] = {};
    int cc = 0;
    for (int k0 = 0; k0 < K; k0 += BK, cc++) {
        #pragma unroll
        for (int i = 0; i < 4; i++) {
            int idx = tid + i * 256;
            int r = idx / BK;
            int e = idx % BK;
            As[e][r] = Ab[(long)(m0 + r) * K + k0 + e];
            int kk = idx / BN;
            int nn = idx % BN;
            Bs[kk][nn] = Bb[(long)(k0 + kk) * N + n0 + nn];
        }
        __syncthreads();
        #pragma unroll
        for (int e = 0; e < BK; e++) {
            float a[4], b[4];
            #pragma unroll
            for (int i = 0; i < 4; i++) a[i] = As[e][ty * 4 + i];
            #pragma unroll
            for (int j = 0; j < 4; j++) b[j] = Bs[e][tx * 4 + j];
            #pragma unroll
            for (int i = 0; i < 4; i++)
                #pragma unroll
                for (int j = 0; j < 4; j++)
                    acc[i][j] += a[i] * b[j];
        }
        __syncthreads();
        if ((cc & 7) == 7) FLUSH_ACC();
    }
    FLUSH_ACC();
    #pragma unroll
    for (int i = 0; i < 4; i++) {
        int m = m0 + ty * 4 + i;
        #pragma unroll
        for (int j = 0; j < 4; j++) {
            int n = n0 + tx * 4 + j;
            float val = beta * tot[i][j];
            if (L) val += alpha * L[(long)blockIdx.z * sL + (long)m * N + n];
            Cb[(long)m * N + n] = val;
        }
    }
}

// High-ILP symmetric-output NN gemm: 128x128 tile, 8x8 per thread.
// C = beta*(A@B) + alpha*L (L batched symmetric or null). Result symmetric:
// computes upper-triangle tiles (bi<=bj), mirror-writes transpose.
// k-order and binning identical to the 64x64 version => bit-identical sums.
__global__ void __launch_bounds__(256, 1)
gemm_nn_sym128(const float* __restrict__ A, const float* __restrict__ Bmat,
               const float* __restrict__ L, float* __restrict__ C,
               float alpha, float beta) {
    __shared__ float As[16][132];   // padded: 2-way max conflict on transpose STS
    __shared__ float Bs[16][128];
    const long SSL = (long)SS * SS;
    const float* Ab = A + (long)blockIdx.z * SSL;
    const float* Bb = Bmat + (long)blockIdx.z * SSL;
    const float* Lb = L ? (L + (long)blockIdx.z * SSL) : (const float*)0;
    float* Cb = C + (long)blockIdx.z * SSL;
    int bi, bj;
    decode_tri8(blockIdx.x, bi, bj);
    const int m0 = bi * 128;
    const int n0 = bj * 128;
    const int tid = threadIdx.x;
    const int tx = tid & 15;        // n direction
    const int ty = tid >> 4;        // m direction
    float acc[8][8] = {};
    float tot[8][8] = {};
    // load decomposition (per 128x16 tile = 512 float4, 256 threads x 2)
    const int ar0 = tid >> 2;            // A row 0..63 (+64 second it)
    const int akv = tid & 3;             // A k-vec 0..3
    const int bk0 = tid >> 5;            // B k row 0..7 (+8 second it)
    const int bnv = tid & 31;            // B n-vec 0..31
    int cc = 0;
    for (int k0 = 0; k0 < SS; k0 += 16, cc++) {
        #pragma unroll
        for (int it = 0; it < 2; it++) {
            int r = ar0 + it * 64;
            float4 av = *(const float4*)&Ab[(long)(m0 + r) * SS + k0 + akv * 4];
            As[akv * 4 + 0][r] = av.x;
            As[akv * 4 + 1][r] = av.y;
            As[akv * 4 + 2][r] = av.z;
            As[akv * 4 + 3][r] = av.w;
            int kk = bk0 + it * 8;
            *(float4*)&Bs[kk][bnv * 4] =
                *(const float4*)&Bb[(long)(k0 + kk) * SS + n0 + bnv * 4];
        }
        __syncthreads();
        #pragma unroll
        for (int e = 0; e < 16; e++) {
            float a[8], b[8];
            *(float4*)&a[0] = *(const float4*)&As[e][ty * 8];
            *(float4*)&a[4] = *(const float4*)&As[e][ty * 8 + 4];
            *(float4*)&b[0] = *(const float4*)&Bs[e][tx * 8];
            *(float4*)&b[4] = *(const float4*)&Bs[e][tx * 8 + 4];
            #pragma unroll
            for (int i = 0; i < 8; i++)
                #pragma unroll
                for (int j = 0; j < 8; j++)
                    acc[i][j] += a[i] * b[j];
        }
        __syncthreads();
        if ((cc & 7) == 7) FLUSH_ACC8();
    }
    FLUSH_ACC8();
    const bool mirror = (bi != bj);
    #pragma unroll
    for (int i = 0; i < 8; i++) {
        int m = m0 + ty * 8 + i;
        #pragma unroll
        for (int j = 0; j < 8; j++) {
            int n = n0 + tx * 8 + j;
            float val = beta * tot[i][j];
            if (Lb) val += alpha * Lb[(long)m * SS + n];
            Cb[(long)m * SS + n] = val;
            if (mirror) Cb[(long)n * SS + m] = val;
        }
    }
}

// X0[i,j] = (float)(( sum_m A[m,i]A[m,j] (fp64) - tau*delta_ij ) / (1.3*lam1))
// Upper-triangle blocks only + mirror write (output symmetric by construction).
__global__ void syrk_buildX0_f64(const float* __restrict__ A,
                                 const float* __restrict__ scal, float* __restrict__ X) {
    __shared__ float As[BK][BM];
    __shared__ float Bs[BK][BN];
    const int b = blockIdx.z;
    const float* Ab = A + (long)b * SS * SS;
    float* Xb = X + (long)b * SS * SS;
    int bi, bj;
    decode_tri(blockIdx.x, bi, bj);
    const int i0 = bi * BM;
    const int j0 = bj * BN;
    const int tid = threadIdx.x;
    const int tx = tid & 15;
    const int ty = tid >> 4;
    double acc[4][4] = {};
    for (int k0 = 0; k0 < SS; k0 += BK) {
        #pragma unroll
        for (int t = 0; t < 4; t++) {
            int idx = tid + t * 256;
            int kk = idx / BN;
            int rr = idx % BN;
            As[kk][rr] = Ab[(long)(k0 + kk) * SS + i0 + rr];
            Bs[kk][rr] = Ab[(long)(k0 + kk) * SS + j0 + rr];
        }
        __syncthreads();
        #pragma unroll
        for (int e = 0; e < BK; e++) {
            float a[4], bb[4];
            #pragma unroll
            for (int i = 0; i < 4; i++) a[i] = As[e][ty * 4 + i];
            #pragma unroll
            for (int j = 0; j < 4; j++) bb[j] = Bs[e][tx * 4 + j];
            #pragma unroll
            for (int i = 0; i < 4; i++)
                #pragma unroll
                for (int j = 0; j < 4; j++)
                    acc[i][j] += (double)a[i] * (double)bb[j];
        }
        __syncthreads();
    }
    const double lam1 = (double)scal[b * 8 + 0];
    const double tau  = TOL2 * lam1;
    const double inv_s = 1.0 / (1.3 * lam1);
    const bool mirror = (bi != bj);
    #pragma unroll
    for (int i = 0; i < 4; i++) {
        int ii = i0 + ty * 4 + i;
        #pragma unroll
        for (int j = 0; j < 4; j++) {
            int jj = j0 + tx * 4 + j;
            double val = acc[i][j];
            if (ii == jj) val -= tau;
            float f = (float)(val * inv_s);
            Xb[(long)ii * SS + jj] = f;
            if (mirror) Xb[(long)jj * SS + ii] = f;
        }
    }
}

// In-place row softmax, one block per row of 1024
__global__ void softmax_rows(float* __restrict__ A) {
    float* row = A + (long)blockIdx.x * SS;
    const int t = threadIdx.x;
    __shared__ float red[256];
    float v[4];
    float mx = -1e30f;
    #pragma unroll
    for (int i = 0; i < 4; i++) { v[i] = row[t + i * 256]; mx = fmaxf(mx, v[i]); }
    red[t] = mx; __syncthreads();
    for (int s = 128; s > 0; s >>= 1) { if (t < s) red[t] = fmaxf(red[t], red[t + s]); __syncthreads(); }
    mx = red[0]; __syncthreads();
    float sum = 0.f;
    #pragma unroll
    for (int i = 0; i < 4; i++) { v[i] = expf(v[i] - mx); sum += v[i]; }
    red[t] = sum; __syncthreads();
    for (int s = 128; s > 0; s >>= 1) { if (t < s) red[t] += red[t + s]; __syncthreads(); }
    const float inv = 1.f / red[0];
    #pragma unroll
    for (int i = 0; i < 4; i++) row[t + i * 256] = v[i] * inv;
}

// ---------------- small vector kernels ----------------
__global__ void k_fill(float* x, float val) {
    int i = blockIdx.x * blockDim.x + threadIdx.x;
    if (i < NB * SS) x[i] = val;
}
// z[b,:] = M[b] x[b,:]  : warp per row
__global__ void k_matvec(const float* __restrict__ M, const float* __restrict__ x,
                         float* __restrict__ y) {
    int b = blockIdx.y;
    int wid = threadIdx.x >> 5;
    int lane = threadIdx.x & 31;
    int row = blockIdx.x * 8 + wid;
    const float* Mb = M + (long)b * SS * SS + (long)row * SS;
    const float* xb = x + b * SS;
    float s = 0.f;
    for (int j = lane; j < SS; j += 32) s += Mb[j] * xb[j];
    #pragma unroll
    for (int o = 16; o > 0; o >>= 1) s += __shfl_down_sync(0xffffffffu, s, o);
    if (lane == 0) y[b * SS + row] = s;
}
// y[b,j] = sum_m A[b,m,j] z[b,m]
__global__ void k_matvecT(const float* __restrict__ A, const float* __restrict__ z,
                          float* __restrict__ y) {
    __shared__ float zs[SS];
    int b = blockIdx.y;
    int j = blockIdx.x * 256 + threadIdx.x;
    const float* Ab = A + (long)b * SS * SS;
    for (int m = threadIdx.x; m < SS; m += 256) zs[m] = z[b * SS + m];
    __syncthreads();
    float s = 0.f;
    for (int m = 0; m < SS; m++) s += Ab[(long)m * SS + j] * zs[m];
    y[b * SS + j] = s;
}
// x = y/||y||, store ||y|| in scal[b*8+slot]
__global__ void k_normalize(const float* __restrict__ y, float* __restrict__ x,
                            float* __restrict__ scal, int slot) {
    int b = blockIdx.x, t = threadIdx.x;
    __shared__ float red[256];
    const float* yb = y + b * SS;
    float v[4]; float ss = 0.f;
    #pragma unroll
    for (int i = 0; i < 4; i++) { v[i] = yb[t + i * 256]; ss += v[i] * v[i]; }
    red[t] = ss; __syncthreads();
    for (int s = 128; s > 0; s >>= 1) { if (t < s) red[t] += red[t + s]; __syncthreads(); }
    float nrm = sqrtf(red[0]);
    if (t == 0) scal[b * 8 + slot] = nrm;
    float inv = 1.f / nrm;
    #pragma unroll
    for (int i = 0; i < 4; i++) x[b * SS + t + i * 256] = v[i] * inv;
}
// W = 0.5*(V + Y)
__global__ void k_combine2(const float* __restrict__ V, const float* __restrict__ Y,
                           float* __restrict__ W) {
    long idx = (long)blockIdx.x * blockDim.x + threadIdx.x;
    if (idx >= (long)NB * SS * DVV) return;
    W[idx] = 0.5f * (V[idx] + Y[idx]);
}

extern "C" void kernel_launch(void* const* d_in, const int* in_sizes, int n_in,
                              void* d_out, int out_size) {
    const float* query_in = (const float*)d_in[0];
    const float* key_in   = (const float*)d_in[1];
    const float* value_in = (const float*)d_in[2];
    const float* Wq = (const float*)d_in[3];
    const float* bq = (const float*)d_in[4];
    const float* Wk = (const float*)d_in[5];
    const float* bk = (const float*)d_in[6];
    const float* Wv = (const float*)d_in[7];
    const float* bv = (const float*)d_in[8];
    float* out = (float*)d_out;

    float *q, *k, *v, *attn, *X, *X2, *Xn, *W, *vx, *vy, *vz, *scal;
    cudaGetSymbolAddress((void**)&q, g_q);
    cudaGetSymbolAddress((void**)&k, g_k);
    cudaGetSymbolAddress((void**)&v, g_v);
    cudaGetSymbolAddress((void**)&attn, g_attn);
    cudaGetSymbolAddress((void**)&X, g_X);
    cudaGetSymbolAddress((void**)&X2, g_X2);
    cudaGetSymbolAddress((void**)&Xn, g_Xn);
    cudaGetSymbolAddress((void**)&W, g_W);
    cudaGetSymbolAddress((void**)&vx, g_vx);
    cudaGetSymbolAddress((void**)&vy, g_vy);
    cudaGetSymbolAddress((void**)&vz, g_vz);
    cudaGetSymbolAddress((void**)&scal, g_scal);

    const float scaling = 0.21022410381342863f;  // 512^-0.25
    const long SSS = (long)SS * SS;
    const long SDV = (long)SS * DVV;

    // ---- projections ----
    {
        dim3 grid(DKK / BN, (NB * SS) / BM, 1);
        gemm_nt<<<grid, 256>>>(query_in, Wq, q, NB * SS, DKK, EE, 0, 0, 0, bq, scaling);
        gemm_nt<<<grid, 256>>>(key_in,   Wk, k, NB * SS, DKK, EE, 0, 0, 0, bk, scaling);
        gemm_nt<<<grid, 256>>>(value_in, Wv, v, NB * SS, DVV, EE, 0, 0, 0, bv, 1.0f);
    }
    // ---- A = softmax(q k^T) ----
    {
        dim3 grid(SS / BN, SS / BM, NB);
        gemm_nt<<<grid, 256>>>(q, k, attn, SS, SS, DKK,
                               (long)SS * DKK, (long)SS * DKK, SSS, nullptr, 1.0f);
    }
    softmax_rows<<<NB * SS, 256>>>(attn);

    // ---- power iteration for lam1 of G = A^T A (matvec-based; only lam1 needed) ----
    k_fill<<<(NB * SS + 255) / 256, 256>>>(vx, 0.03125f);
    for (int it = 0; it < POW_ITERS; it++) {
        k_matvec<<<dim3(SS / 8, NB), 256>>>(attn, vx, vz);    // vz = A vx
        k_matvecT<<<dim3(SS / 256, NB), 256>>>(attn, vz, vy); // vy = A^T vz
        k_normalize<<<NB, 256>>>(vy, vx, scal, 0);            // slot0 -> lam1
    }

    // ---- X0 = (A^T A - tau I) / (1.3 lam1), fp64 fused, upper-tri + mirror ----
    {
        dim3 grid(NPAIRS, 1, NB);
        syrk_buildX0_f64<<<grid, 256>>>(attn, scal, X);
    }

    // ---- Over-relaxed Newton-Schulz sign: X <- a X - (a-1) X^3 ----
    // Symmetric iterates => 128x128 sym-half high-ILP GEMMs.
    float* Xa = X;
    float* Xb = Xn;
    dim3 gridNS(NP8, 1, NB);
    for (int it = 0; it < NS_GROW + NS_POLISH; it++) {
        float a = (it < NS_GROW) ? 1.9f : 1.5f;
        gemm_nn_sym128<<<gridNS, 256>>>(Xa, Xa, nullptr, X2, 0.f, 1.f);
        gemm_nn_sym128<<<gridNS, 256>>>(X2, Xa, Xa, Xb, a, -(a - 1.0f));
        float* t = Xa; Xa = Xb; Xb = t;
    }

    // ---- Y = X V  (into X2) ----
    {
        dim3 grid(DVV / BN, SS / BM, NB);
        gemm_nn_ep<<<grid, 256>>>(Xa, v, nullptr, X2, SS, DVV, SS,
                                  SSS, SDV, 0, SDV, 0.f, 1.f);
    }
    // ---- W = 0.5 (V + Y) ----
    {
        long total = (long)NB * SS * DVV;
        k_combine2<<<(unsigned)((total + 255) / 256), 256>>>(v, X2, W);
    }
    // ---- out = A W ----
    {
        dim3 grid(DVV / BN, SS / BM, NB);
        gemm_nn_ep<<<grid, 256>>>(attn, W, nullptr, out, SS, DVV, SS,
                                  SSS, SDV, 0, SDV, 0.f, 1.f);
    }
}

// round 15
// speedup vs baseline: 2.2156x; 1.0931x over previous
#include <cuda_runtime.h>
#include <math.h>

#define NB 8
#define SS 1024
#define EE 1024
#define DKK 512
#define DVV 512

#define NS_GROW 26      // a = 1.9 iterations
#define NS_POLISH 6     // a = 1.5 iterations
#define POW_ITERS 8
#define TOL2 1.4901161193847656e-6   // (10*1024*eps_fp32)^2, double

#define NT 16           // 64-px tile grid (X0 build)
#define NPAIRS 136
#define NT8 8           // 128-px tile grid (NS loop)
#define NP8 36          // NT8*(NT8+1)/2

// ---------------- scratch (static device globals) ----------------
__device__ float g_q[NB * SS * DKK];
__device__ float g_k[NB * SS * DKK];
__device__ float g_v[NB * SS * DVV];
__device__ float g_attn[NB * SS * SS];
__device__ float g_X[NB * SS * SS];
__device__ float g_X2[NB * SS * SS];
__device__ float g_Xn[NB * SS * SS];
__device__ float g_W[NB * SS * DVV];
__device__ float g_vx[NB * SS];
__device__ float g_vy[NB * SS];
__device__ float g_vz[NB * SS];
__device__ float g_scal[NB * 8];  // slot0 = lam1

#define BM 64
#define BN 64
#define BK 16

#define FLUSH_ACC() do { \
    _Pragma("unroll") \
    for (int _i = 0; _i < 4; _i++) \
        _Pragma("unroll") \
        for (int _j = 0; _j < 4; _j++) { tot[_i][_j] += acc[_i][_j]; acc[_i][_j] = 0.f; } \
} while (0)

#define FLUSH_ACC8() do { \
    _Pragma("unroll") \
    for (int _i = 0; _i < 8; _i++) \
        _Pragma("unroll") \
        for (int _j = 0; _j < 8; _j++) { tot[_i][_j] += acc[_i][_j]; acc[_i][_j] = 0.f; } \
} while (0)

__device__ __forceinline__ void decode_tri(int t, int& bi, int& bj) {
    int rem = t;
    int i = 0;
    while (rem >= NT - i) { rem -= NT - i; i++; }
    bi = i;
    bj = i + rem;
}
__device__ __forceinline__ void decode_tri8(int t, int& bi, int& bj) {
    int rem = t;
    int i = 0;
    while (rem >= NT8 - i) { rem -= NT8 - i; i++; }
    bi = i;
    bj = i + rem;
}

// C[m,n] = scale*( sum_e A[m,e]*B[n,e] + bias[n] )  (NT), binned accumulation
__global__ void gemm_nt(const float* __restrict__ A, const float* __restrict__ Bmat,
                        float* __restrict__ C, int M, int N, int E,
                        long sA, long sB, long sC,
                        const float* __restrict__ bias, float scale) {
    __shared__ float As[BK][BM];
    __shared__ float Bs[BK][BN];
    const float* Ab = A + (long)blockIdx.z * sA;
    const float* Bb = Bmat + (long)blockIdx.z * sB;
    float* Cb = C + (long)blockIdx.z * sC;
    const int m0 = blockIdx.y * BM;
    const int n0 = blockIdx.x * BN;
    const int tid = threadIdx.x;
    const int tx = tid & 15;
    const int ty = tid >> 4;
    float acc[4][4] = {};
    float tot[4][4] = {};
    int cc = 0;
    for (int e0 = 0; e0 < E; e0 += BK, cc++) {
        #pragma unroll
        for (int i = 0; i < 4; i++) {
            int idx = tid + i * 256;
            int r = idx / BK;
            int e = idx % BK;
            As[e][r] = Ab[(long)(m0 + r) * E + e0 + e];
            Bs[e][r] = Bb[(long)(n0 + r) * E + e0 + e];
        }
        __syncthreads();
        #pragma unroll
        for (int e = 0; e < BK; e++) {
            float a[4], b[4];
            #pragma unroll
            for (int i = 0; i < 4; i++) a[i] = As[e][ty * 4 + i];
            #pragma unroll
            for (int j = 0; j < 4; j++) b[j] = Bs[e][tx * 4 + j];
            #pragma unroll
            for (int i = 0; i < 4; i++)
                #pragma unroll
                for (int j = 0; j < 4; j++)
                    acc[i][j] += a[i] * b[j];
        }
        __syncthreads();
        if ((cc & 7) == 7) FLUSH_ACC();
    }
    FLUSH_ACC();
    #pragma unroll
    for (int i = 0; i < 4; i++) {
        int m = m0 + ty * 4 + i;
        #pragma unroll
        for (int j = 0; j < 4; j++) {
            int n = n0 + tx * 4 + j;
            float val = tot[i][j];
            if (bias) val += bias[n];
            Cb[(long)m * N + n] = scale * val;
        }
    }
}

// C[m,n] = beta * sum_k A[m,k]*B[k,n]  (+ alpha*L[m,n] if L)   (NN), binned
__global__ void gemm_nn_ep(const float* __restrict__ A, const float* __restrict__ Bmat,
                           const float* __restrict__ L, float* __restrict__ C,
                           int M, int N, int K,
                           long sA, long sB, long sL, long sC,
                           float alpha, float beta) {
    __shared__ float As[BK][BM];
    __shared__ float Bs[BK][BN];
    const float* Ab = A + (long)blockIdx.z * sA;
    const float* Bb = Bmat + (long)blockIdx.z * sB;
    float* Cb = C + (long)blockIdx.z * sC;
    const int m0 = blockIdx.y * BM;
    const int n0 = blockIdx.x * BN;
    const int tid = threadIdx.x;
    const int tx = tid & 15;
    const int ty = tid >> 4;
    float acc[4][4] = {};
    float tot[4][4] = {};
    int cc = 0;
    for (int k0 = 0; k0 < K; k0 += BK, cc++) {
        #pragma unroll
        for (int i = 0; i < 4; i++) {
            int idx = tid + i * 256;
            int r = idx / BK;
            int e = idx % BK;
            As[e][r] = Ab[(long)(m0 + r) * K + k0 + e];
            int kk = idx / BN;
            int nn = idx % BN;
            Bs[kk][nn] = Bb[(long)(k0 + kk) * N + n0 + nn];
        }
        __syncthreads();
        #pragma unroll
        for (int e = 0; e < BK; e++) {
            float a[4], b[4];
            #pragma unroll
            for (int i = 0; i < 4; i++) a[i] = As[e][ty * 4 + i];
            #pragma unroll
            for (int j = 0; j < 4; j++) b[j] = Bs[e][tx * 4 + j];
            #pragma unroll
            for (int i = 0; i < 4; i++)
                #pragma unroll
                for (int j = 0; j < 4; j++)
                    acc[i][j] += a[i] * b[j];
        }
        __syncthreads();
        if ((cc & 7) == 7) FLUSH_ACC();
    }
    FLUSH_ACC();
    #pragma unroll
    for (int i = 0; i < 4; i++) {
        int m = m0 + ty * 4 + i;
        #pragma unroll
        for (int j = 0; j < 4; j++) {
            int n = n0 + tx * 4 + j;
            float val = beta * tot[i][j];
            if (L) val += alpha * L[(long)blockIdx.z * sL + (long)m * N + n];
            Cb[(long)m * N + n] = val;
        }
    }
}

// High-ILP symmetric-output NN gemm: 128x128 tile, 8x8 per thread,
// DOUBLE-BUFFERED smem pipeline (prefetch chunk c+1 during compute on c).
// C = beta*(A@B) + alpha*L (L batched symmetric or null). Result symmetric:
// computes upper-triangle tiles (bi<=bj), mirror-writes transpose.
// Accumulation order identical to the single-buffer version.
__global__ void __launch_bounds__(256, 1)
gemm_nn_sym128(const float* __restrict__ A, const float* __restrict__ Bmat,
               const float* __restrict__ L, float* __restrict__ C,
               float alpha, float beta) {
    __shared__ float As[2][16][132];
    __shared__ float Bs[2][16][128];
    const long SSL = (long)SS * SS;
    const float* Ab = A + (long)blockIdx.z * SSL;
    const float* Bb = Bmat + (long)blockIdx.z * SSL;
    const float* Lb = L ? (L + (long)blockIdx.z * SSL) : (const float*)0;
    float* Cb = C + (long)blockIdx.z * SSL;
    int bi, bj;
    decode_tri8(blockIdx.x, bi, bj);
    const int m0 = bi * 128;
    const int n0 = bj * 128;
    const int tid = threadIdx.x;
    const int tx = tid & 15;        // n direction
    const int ty = tid >> 4;        // m direction
    float acc[8][8] = {};
    float tot[8][8] = {};
    // load decomposition (per 128x16 tile = 512 float4, 256 threads x 2)
    const int ar0 = tid >> 2;            // A row 0..63 (+64 second it)
    const int akv = tid & 3;             // A k-vec 0..3
    const int bk0 = tid >> 5;            // B k row 0..7 (+8 second it)
    const int bnv = tid & 31;            // B n-vec 0..31

    float4 av[2], bv[2];
    // prologue: fetch chunk 0
    #pragma unroll
    for (int it = 0; it < 2; it++) {
        av[it] = *(const float4*)&Ab[(long)(m0 + ar0 + it * 64) * SS + akv * 4];
        bv[it] = *(const float4*)&Bb[(long)(bk0 + it * 8) * SS + n0 + bnv * 4];
    }
    #pragma unroll
    for (int it = 0; it < 2; it++) {
        int r = ar0 + it * 64;
        As[0][akv * 4 + 0][r] = av[it].x;
        As[0][akv * 4 + 1][r] = av[it].y;
        As[0][akv * 4 + 2][r] = av[it].z;
        As[0][akv * 4 + 3][r] = av[it].w;
        *(float4*)&Bs[0][bk0 + it * 8][bnv * 4] = bv[it];
    }
    __syncthreads();

    for (int c = 0; c < 64; c++) {
        const int cur = c & 1;
        const bool have_next = (c + 1 < 64);
        if (have_next) {
            const int k0n = (c + 1) * 16;
            #pragma unroll
            for (int it = 0; it < 2; it++) {
                av[it] = *(const float4*)&Ab[(long)(m0 + ar0 + it * 64) * SS + k0n + akv * 4];
                bv[it] = *(const float4*)&Bb[(long)(k0n + bk0 + it * 8) * SS + n0 + bnv * 4];
            }
        }
        #pragma unroll
        for (int e = 0; e < 16; e++) {
            float a[8], b[8];
            *(float4*)&a[0] = *(const float4*)&As[cur][e][ty * 8];
            *(float4*)&a[4] = *(const float4*)&As[cur][e][ty * 8 + 4];
            *(float4*)&b[0] = *(const float4*)&Bs[cur][e][tx * 8];
            *(float4*)&b[4] = *(const float4*)&Bs[cur][e][tx * 8 + 4];
            #pragma unroll
            for (int i = 0; i < 8; i++)
                #pragma unroll
                for (int j = 0; j < 8; j++)
                    acc[i][j] += a[i] * b[j];
        }
        if (have_next) {
            const int nxt = cur ^ 1;
            #pragma unroll
            for (int it = 0; it < 2; it++) {
                int r = ar0 + it * 64;
                As[nxt][akv * 4 + 0][r] = av[it].x;
                As[nxt][akv * 4 + 1][r] = av[it].y;
                As[nxt][akv * 4 + 2][r] = av[it].z;
                As[nxt][akv * 4 + 3][r] = av[it].w;
                *(float4*)&Bs[nxt][bk0 + it * 8][bnv * 4] = bv[it];
            }
        }
        __syncthreads();
        if ((c & 7) == 7) FLUSH_ACC8();
    }
    FLUSH_ACC8();
    const bool mirror = (bi != bj);
    #pragma unroll
    for (int i = 0; i < 8; i++) {
        int m = m0 + ty * 8 + i;
        #pragma unroll
        for (int j = 0; j < 8; j++) {
            int n = n0 + tx * 8 + j;
            float val = beta * tot[i][j];
            if (Lb) val += alpha * Lb[(long)m * SS + n];
            Cb[(long)m * SS + n] = val;
            if (mirror) Cb[(long)n * SS + m] = val;
        }
    }
}

// X0[i,j] = (float)(( sum_m A[m,i]A[m,j] (fp64) - tau*delta_ij ) / (1.3*lam1))
// Upper-triangle blocks only + mirror write (output symmetric by construction).
__global__ void syrk_buildX0_f64(const float* __restrict__ A,
                                 const float* __restrict__ scal, float* __restrict__ X) {
    __shared__ float As[BK][BM];
    __shared__ float Bs[BK][BN];
    const int b = blockIdx.z;
    const float* Ab = A + (long)b * SS * SS;
    float* Xb = X + (long)b * SS * SS;
    int bi, bj;
    decode_tri(blockIdx.x, bi, bj);
    const int i0 = bi * BM;
    const int j0 = bj * BN;
    const int tid = threadIdx.x;
    const int tx = tid & 15;
    const int ty = tid >> 4;
    double acc[4][4] = {};
    for (int k0 = 0; k0 < SS; k0 += BK) {
        #pragma unroll
        for (int t = 0; t < 4; t++) {
            int idx = tid + t * 256;
            int kk = idx / BN;
            int rr = idx % BN;
            As[kk][rr] = Ab[(long)(k0 + kk) * SS + i0 + rr];
            Bs[kk][rr] = Ab[(long)(k0 + kk) * SS + j0 + rr];
        }
        __syncthreads();
        #pragma unroll
        for (int e = 0; e < BK; e++) {
            float a[4], bb[4];
            #pragma unroll
            for (int i = 0; i < 4; i++) a[i] = As[e][ty * 4 + i];
            #pragma unroll
            for (int j = 0; j < 4; j++) bb[j] = Bs[e][tx * 4 + j];
            #pragma unroll
            for (int i = 0; i < 4; i++)
                #pragma unroll
                for (int j = 0; j < 4; j++)
                    acc[i][j] += (double)a[i] * (double)bb[j];
        }
        __syncthreads();
    }
    const double lam1 = (double)scal[b * 8 + 0];
    const double tau  = TOL2 * lam1;
    const double inv_s = 1.0 / (1.3 * lam1);
    const bool mirror = (bi != bj);
    #pragma unroll
    for (int i = 0; i < 4; i++) {
        int ii = i0 + ty * 4 + i;
        #pragma unroll
        for (int j = 0; j < 4; j++) {
            int jj = j0 + tx * 4 + j;
            double val = acc[i][j];
            if (ii == jj) val -= tau;
            float f = (float)(val * inv_s);
            Xb[(long)ii * SS + jj] = f;
            if (mirror) Xb[(long)jj * SS + ii] = f;
        }
    }
}

// In-place row softmax, one block per row of 1024
__global__ void softmax_rows(float* __restrict__ A) {
    float* row = A + (long)blockIdx.x * SS;
    const int t = threadIdx.x;
    __shared__ float red[256];
    float v[4];
    float mx = -1e30f;
    #pragma unroll
    for (int i = 0; i < 4; i++) { v[i] = row[t + i * 256]; mx = fmaxf(mx, v[i]); }
    red[t] = mx; __syncthreads();
    for (int s = 128; s > 0; s >>= 1) { if (t < s) red[t] = fmaxf(red[t], red[t + s]); __syncthreads(); }
    mx = red[0]; __syncthreads();
    float sum = 0.f;
    #pragma unroll
    for (int i = 0; i < 4; i++) { v[i] = expf(v[i] - mx); sum += v[i]; }
    red[t] = sum; __syncthreads();
    for (int s = 128; s > 0; s >>= 1) { if (t < s) red[t] += red[t + s]; __syncthreads(); }
    const float inv = 1.f / red[0];
    #pragma unroll
    for (int i = 0; i < 4; i++) row[t + i * 256] = v[i] * inv;
}

// ---------------- small vector kernels ----------------
__global__ void k_fill(float* x, float val) {
    int i = blockIdx.x * blockDim.x + threadIdx.x;
    if (i < NB * SS) x[i] = val;
}
// z[b,:] = M[b] x[b,:]  : warp per row
__global__ void k_matvec(const float* __restrict__ M, const float* __restrict__ x,
                         float* __restrict__ y) {
    int b = blockIdx.y;
    int wid = threadIdx.x >> 5;
    int lane = threadIdx.x & 31;
    int row = blockIdx.x * 8 + wid;
    const float* Mb = M + (long)b * SS * SS + (long)row * SS;
    const float* xb = x + b * SS;
    float s = 0.f;
    for (int j = lane; j < SS; j += 32) s += Mb[j] * xb[j];
    #pragma unroll
    for (int o = 16; o > 0; o >>= 1) s += __shfl_down_sync(0xffffffffu, s, o);
    if (lane == 0) y[b * SS + row] = s;
}
// y[b,j] = sum_m A[b,m,j] z[b,m]
__global__ void k_matvecT(const float* __restrict__ A, const float* __restrict__ z,
                          float* __restrict__ y) {
    __shared__ float zs[SS];
    int b = blockIdx.y;
    int j = blockIdx.x * 256 + threadIdx.x;
    const float* Ab = A + (long)b * SS * SS;
    for (int m = threadIdx.x; m < SS; m += 256) zs[m] = z[b * SS + m];
    __syncthreads();
    float s = 0.f;
    for (int m = 0; m < SS; m++) s += Ab[(long)m * SS + j] * zs[m];
    y[b * SS + j] = s;
}
// x = y/||y||, store ||y|| in scal[b*8+slot]
__global__ void k_normalize(const float* __restrict__ y, float* __restrict__ x,
                            float* __restrict__ scal, int slot) {
    int b = blockIdx.x, t = threadIdx.x;
    __shared__ float red[256];
    const float* yb = y + b * SS;
    float v[4]; float ss = 0.f;
    #pragma unroll
    for (int i = 0; i < 4; i++) { v[i] = yb[t + i * 256]; ss += v[i] * v[i]; }
    red[t] = ss; __syncthreads();
    for (int s = 128; s > 0; s >>= 1) { if (t < s) red[t] += red[t + s]; __syncthreads(); }
    float nrm = sqrtf(red[0]);
    if (t == 0) scal[b * 8 + slot] = nrm;
    float inv = 1.f / nrm;
    #pragma unroll
    for (int i = 0; i < 4; i++) x[b * SS + t + i * 256] = v[i] * inv;
}
// W = 0.5*(V + Y)
__global__ void k_combine2(const float* __restrict__ V, const float* __restrict__ Y,
                           float* __restrict__ W) {
    long idx = (long)blockIdx.x * blockDim.x + threadIdx.x;
    if (idx >= (long)NB * SS * DVV) return;
    W[idx] = 0.5f * (V[idx] + Y[idx]);
}

extern "C" void kernel_launch(void* const* d_in, const int* in_sizes, int n_in,
                              void* d_out, int out_size) {
    const float* query_in = (const float*)d_in[0];
    const float* key_in   = (const float*)d_in[1];
    const float* value_in = (const float*)d_in[2];
    const float* Wq = (const float*)d_in[3];
    const float* bq = (const float*)d_in[4];
    const float* Wk = (const float*)d_in[5];
    const float* bk = (const float*)d_in[6];
    const float* Wv = (const float*)d_in[7];
    const float* bv = (const float*)d_in[8];
    float* out = (float*)d_out;

    float *q, *k, *v, *attn, *X, *X2, *Xn, *W, *vx, *vy, *vz, *scal;
    cudaGetSymbolAddress((void**)&q, g_q);
    cudaGetSymbolAddress((void**)&k, g_k);
    cudaGetSymbolAddress((void**)&v, g_v);
    cudaGetSymbolAddress((void**)&attn, g_attn);
    cudaGetSymbolAddress((void**)&X, g_X);
    cudaGetSymbolAddress((void**)&X2, g_X2);
    cudaGetSymbolAddress((void**)&Xn, g_Xn);
    cudaGetSymbolAddress((void**)&W, g_W);
    cudaGetSymbolAddress((void**)&vx, g_vx);
    cudaGetSymbolAddress((void**)&vy, g_vy);
    cudaGetSymbolAddress((void**)&vz, g_vz);
    cudaGetSymbolAddress((void**)&scal, g_scal);

    const float scaling = 0.21022410381342863f;  // 512^-0.25
    const long SSS = (long)SS * SS;
    const long SDV = (long)SS * DVV;

    // ---- projections ----
    {
        dim3 grid(DKK / BN, (NB * SS) / BM, 1);
        gemm_nt<<<grid, 256>>>(query_in, Wq, q, NB * SS, DKK, EE, 0, 0, 0, bq, scaling);
        gemm_nt<<<grid, 256>>>(key_in,   Wk, k, NB * SS, DKK, EE, 0, 0, 0, bk, scaling);
        gemm_nt<<<grid, 256>>>(value_in, Wv, v, NB * SS, DVV, EE, 0, 0, 0, bv, 1.0f);
    }
    // ---- A = softmax(q k^T) ----
    {
        dim3 grid(SS / BN, SS / BM, NB);
        gemm_nt<<<grid, 256>>>(q, k, attn, SS, SS, DKK,
                               (long)SS * DKK, (long)SS * DKK, SSS, nullptr, 1.0f);
    }
    softmax_rows<<<NB * SS, 256>>>(attn);

    // ---- power iteration for lam1 of G = A^T A (matvec-based; only lam1 needed) ----
    k_fill<<<(NB * SS + 255) / 256, 256>>>(vx, 0.03125f);
    for (int it = 0; it < POW_ITERS; it++) {
        k_matvec<<<dim3(SS / 8, NB), 256>>>(attn, vx, vz);    // vz = A vx
        k_matvecT<<<dim3(SS / 256, NB), 256>>>(attn, vz, vy); // vy = A^T vz
        k_normalize<<<NB, 256>>>(vy, vx, scal, 0);            // slot0 -> lam1
    }

    // ---- X0 = (A^T A - tau I) / (1.3 lam1), fp64 fused, upper-tri + mirror ----
    {
        dim3 grid(NPAIRS, 1, NB);
        syrk_buildX0_f64<<<grid, 256>>>(attn, scal, X);
    }

    // ---- Over-relaxed Newton-Schulz sign: X <- a X - (a-1) X^3 ----
    // Symmetric iterates => 128x128 sym-half double-buffered GEMMs.
    float* Xa = X;
    float* Xb = Xn;
    dim3 gridNS(NP8, 1, NB);
    for (int it = 0; it < NS_GROW + NS_POLISH; it++) {
        float a = (it < NS_GROW) ? 1.9f : 1.5f;
        gemm_nn_sym128<<<gridNS, 256>>>(Xa, Xa, nullptr, X2, 0.f, 1.f);
        gemm_nn_sym128<<<gridNS, 256>>>(X2, Xa, Xa, Xb, a, -(a - 1.0f));
        float* t = Xa; Xa = Xb; Xb = t;
    }

    // ---- Y = X V  (into X2) ----
    {
        dim3 grid(DVV / BN, SS / BM, NB);
        gemm_nn_ep<<<grid, 256>>>(Xa, v, nullptr, X2, SS, DVV, SS,
                                  SSS, SDV, 0, SDV, 0.f, 1.f);
    }
    // ---- W = 0.5 (V + Y) ----
    {
        long total = (long)NB * SS * DVV;
        k_combine2<<<(unsigned)((total + 255) / 256), 256>>>(v, X2, W);
    }
    // ---- out = A W ----
    {
        dim3 grid(DVV / BN, SS / BM, NB);
        gemm_nn_ep<<<grid, 256>>>(attn, W, nullptr, out, SS, DVV, SS,
                                  SSS, SDV, 0, SDV, 0.f, 1.f);
    }
}